// round 9
// baseline (speedup 1.0000x reference)
#include <cuda_runtime.h>

// CenterLoss: loss = (1/B) * sum_i [ sxx/m^2 + scc - 2*sxc/m ],  m = max(sqrt(sxx),1e-12)
// B=16384, C=8192, D=64.
// R9 = R8 chain structure + finer wave granularity + streaming hint on x.
//  - 1024 blocks x 128 threads (16 rows/block): blocks/SM skew 7/6 vs 4/3
//  - x loaded with __ldcs (read-once, evict-first) so gathered centers stay in L2
//  - speculative int32 gather off lpair; probe+ballot resolve dtype off-chain
//  - block reduce -> 1 fp32 atomic + 1 counter atomic per block

#define EPS 1e-12f
#define R 2   // rows per half-warp

__device__ float g_acc;            // zero at load; reset by finalizer each run
__device__ unsigned int g_count;

__global__ void __launch_bounds__(128)
center_loss_kernel(const float4* __restrict__ x,
                   const void* __restrict__ labels,
                   const float4* __restrict__ centers,
                   float* __restrict__ out,
                   float inv_batch)
{
    __shared__ float ssum[4];

    const int tid  = threadIdx.x;
    const int lane = tid & 31;
    const int wid  = tid >> 5;
    const int hw   = lane >> 4;         // half-warp id
    const int sub  = lane & 15;         // lane within half-warp
    const int base = (((blockIdx.x * 4 + wid) * 2) + hw) * R;  // first of R rows

    // ---- chain head: labels first (int32 view, safe/in-bounds for either dtype:
    // an int64 buffer with values in [0,8192) reinterpreted as int32 yields
    // alternating {label, 0}, all valid centers rows) ----
    int2 lpair = ((const int2*)labels)[base >> 1];

    // probe (bytes 4..255, in-bounds for any dtype) — resolved later, off-chain
    unsigned int probe = ((const unsigned int*)labels)[2 * lane + 1];

    // independent x loads fill the label-load shadow; read-once -> streaming
    float4 xv[R];
    #pragma unroll
    for (int i = 0; i < R; ++i)
        xv[i] = __ldcs(&x[(base + i) * 16 + sub]);

    // ---- speculative gather straight off lpair (no ballot in the chain) ----
    int lab[R];
    lab[0] = lpair.x; lab[1] = lpair.y;
    float4 cv[R];
    #pragma unroll
    for (int i = 0; i < R; ++i)
        cv[i] = centers[lab[i] * 16 + sub];

    // dtype resolution overlaps the gather; int64 labels => all probes zero
    bool is32 = __ballot_sync(0xffffffffu, probe != 0u) != 0u;
    if (!is32) {  // int64 correction path (never taken for this dataset)
        #pragma unroll
        for (int i = 0; i < R; ++i) {
            lab[i] = (int)((const long long*)labels)[base + i];
            cv[i]  = centers[lab[i] * 16 + sub];
        }
    }

    // ---- per-row sums + half-warp (16-lane) reduction ----
    float local = 0.0f;
    #pragma unroll
    for (int i = 0; i < R; ++i) {
        float sxx = xv[i].x*xv[i].x + xv[i].y*xv[i].y + xv[i].z*xv[i].z + xv[i].w*xv[i].w;
        float sxc = xv[i].x*cv[i].x + xv[i].y*cv[i].y + xv[i].z*cv[i].z + xv[i].w*cv[i].w;
        float scc = cv[i].x*cv[i].x + cv[i].y*cv[i].y + cv[i].z*cv[i].z + cv[i].w*cv[i].w;
        #pragma unroll
        for (int o = 8; o; o >>= 1) {
            sxx += __shfl_xor_sync(0xffffffffu, sxx, o);
            sxc += __shfl_xor_sync(0xffffffffu, sxc, o);
            scc += __shfl_xor_sync(0xffffffffu, scc, o);
        }
        if (sub == 0) {
            float m = fmaxf(sqrtf(sxx), EPS);
            float r = 1.0f / m;
            local += sxx * r * r + scc - 2.0f * sxc * r;
        }
    }
    // fold the two half-warps into lane 0 of each warp
    local += __shfl_xor_sync(0xffffffffu, local, 16);

    // ---- block reduce: 4 warp partials -> 1 atomic per block ----
    if (lane == 0) ssum[wid] = local;
    __syncthreads();
    if (tid == 0) {
        float s = ssum[0] + ssum[1] + ssum[2] + ssum[3];
        atomicAdd(&g_acc, s);
        __threadfence();
        unsigned int old = atomicAdd(&g_count, 1u);
        if (old == gridDim.x - 1u) {
            float total = atomicExch(&g_acc, 0.0f);
            *out = total * inv_batch;
            g_count = 0u;
        }
    }
}

extern "C" void kernel_launch(void* const* d_in, const int* in_sizes, int n_in,
                              void* d_out, int out_size)
{
    const float4* x       = (const float4*)d_in[0];
    const void*   labels  = d_in[1];
    const float4* centers = (const float4*)d_in[2];
    float*        out     = (float*)d_out;

    const int batch = in_sizes[0] / 64;              // 16384
    const int rows_per_block = 4 * 2 * R;            // 16
    const int blocks = batch / rows_per_block;       // 1024
    center_loss_kernel<<<blocks, 128>>>(x, labels, centers, out,
                                        1.0f / (float)batch);
}

// round 10
// speedup vs baseline: 1.0340x; 1.0340x over previous
#include <cuda_runtime.h>

// CenterLoss: loss = (1/B) * sum_i [ sxx/m^2 + scc - 2*sxc/m ],  m = max(sqrt(sxx),1e-12)
// B=16384, C=8192, D=64.
// R10 = R8 (best measured) + L2 prefetch of the centers table.
//  - each block prefetches its 4KB slice of centers (32 x 128B lines) via
//    prefetch.global.L2, issued before/parallel with the label load. By the
//    time labels arrive, the gather is an L2 hit instead of a DRAM round-trip.
//    No extra DRAM traffic: every centers line is compulsory anyway.
//  - 512 blocks x 256 threads, R=2 rows per half-warp (R8 config)
//  - speculative int32 gather off lpair; probe+ballot resolve dtype off-chain
//  - block reduce -> 1 fp32 atomic + 1 counter atomic per block

#define EPS 1e-12f
#define R 2   // rows per half-warp

__device__ float g_acc;            // zero at load; reset by finalizer each run
__device__ unsigned int g_count;

__global__ void __launch_bounds__(256)
center_loss_kernel(const float4* __restrict__ x,
                   const void* __restrict__ labels,
                   const float4* __restrict__ centers,
                   float* __restrict__ out,
                   float inv_batch)
{
    __shared__ float ssum[8];

    const int tid  = threadIdx.x;
    const int lane = tid & 31;
    const int wid  = tid >> 5;
    const int hw   = lane >> 4;         // half-warp id
    const int sub  = lane & 15;         // lane within half-warp
    const int base = (((blockIdx.x * 8 + wid) * 2) + hw) * R;  // first of R rows

    // ---- L2 prefetch: this block's 4KB slice of centers (32 lines x 128B).
    // Issued first; completes during the label-load epoch. Gather becomes L2-hit.
    if (tid < 32) {
        const char* cbase = (const char*)centers + (size_t)blockIdx.x * 4096 + tid * 128;
        asm volatile("prefetch.global.L2 [%0];" :: "l"(cbase));
    }

    // ---- chain head: labels (int32 view — safe/in-bounds for either dtype:
    // an int64 buffer with values in [0,8192) reinterpreted as int32 yields
    // alternating {label, 0}, all valid centers rows) ----
    int2 lpair = ((const int2*)labels)[base >> 1];

    // probe (bytes 4..255, in-bounds for any dtype) — resolved later, off-chain
    unsigned int probe = ((const unsigned int*)labels)[2 * lane + 1];

    // independent x loads fill the label-load shadow
    float4 xv[R];
    #pragma unroll
    for (int i = 0; i < R; ++i)
        xv[i] = x[(base + i) * 16 + sub];

    // ---- speculative gather straight off lpair (no ballot in the chain) ----
    int lab[R];
    lab[0] = lpair.x; lab[1] = lpair.y;
    float4 cv[R];
    #pragma unroll
    for (int i = 0; i < R; ++i)
        cv[i] = centers[lab[i] * 16 + sub];

    // dtype resolution overlaps the gather; int64 labels => all probes zero
    bool is32 = __ballot_sync(0xffffffffu, probe != 0u) != 0u;
    if (!is32) {  // int64 correction path (never taken for this dataset)
        #pragma unroll
        for (int i = 0; i < R; ++i) {
            lab[i] = (int)((const long long*)labels)[base + i];
            cv[i]  = centers[lab[i] * 16 + sub];
        }
    }

    // ---- per-row sums + half-warp (16-lane) reduction ----
    float local = 0.0f;
    #pragma unroll
    for (int i = 0; i < R; ++i) {
        float sxx = xv[i].x*xv[i].x + xv[i].y*xv[i].y + xv[i].z*xv[i].z + xv[i].w*xv[i].w;
        float sxc = xv[i].x*cv[i].x + xv[i].y*cv[i].y + xv[i].z*cv[i].z + xv[i].w*cv[i].w;
        float scc = cv[i].x*cv[i].x + cv[i].y*cv[i].y + cv[i].z*cv[i].z + cv[i].w*cv[i].w;
        #pragma unroll
        for (int o = 8; o; o >>= 1) {
            sxx += __shfl_xor_sync(0xffffffffu, sxx, o);
            sxc += __shfl_xor_sync(0xffffffffu, sxc, o);
            scc += __shfl_xor_sync(0xffffffffu, scc, o);
        }
        if (sub == 0) {
            float m = fmaxf(sqrtf(sxx), EPS);
            float r = 1.0f / m;
            local += sxx * r * r + scc - 2.0f * sxc * r;
        }
    }
    // fold the two half-warps into lane 0 of each warp
    local += __shfl_xor_sync(0xffffffffu, local, 16);

    // ---- block reduce: 8 warp partials -> 1 atomic per block ----
    if (lane == 0) ssum[wid] = local;
    __syncthreads();
    if (tid == 0) {
        float s = 0.0f;
        #pragma unroll
        for (int i = 0; i < 8; ++i) s += ssum[i];
        atomicAdd(&g_acc, s);
        __threadfence();
        unsigned int old = atomicAdd(&g_count, 1u);
        if (old == gridDim.x - 1u) {
            float total = atomicExch(&g_acc, 0.0f);
            *out = total * inv_batch;
            g_count = 0u;
        }
    }
}

extern "C" void kernel_launch(void* const* d_in, const int* in_sizes, int n_in,
                              void* d_out, int out_size)
{
    const float4* x       = (const float4*)d_in[0];
    const void*   labels  = d_in[1];
    const float4* centers = (const float4*)d_in[2];
    float*        out     = (float*)d_out;

    const int batch = in_sizes[0] / 64;              // 16384
    const int rows_per_block = 8 * 2 * R;            // 32
    const int blocks = batch / rows_per_block;       // 512  (= 2MB centers / 4KB)
    center_loss_kernel<<<blocks, 256>>>(x, labels, centers, out,
                                        1.0f / (float)batch);
}